// round 5
// baseline (speedup 1.0000x reference)
#include <cuda_runtime.h>
#include <cstdint>

// Complex attention via mma.sync tf32 + Karatsuba (3-mult complex GEMMs),
// smem-preconverted tf32 operands, persistent CTAs with dynamic ticketing.

#define S_LEN   2048
#define DH      64
#define QT      128
#define NT      64
#define NTILES  (S_LEN / NT)
#define THREADS 256
#define NITEMS  512            // 16 q-tiles x 32 heads
#define GRID    152
#define QSTR    68
#define VSTR    72

#define QR_F    0
#define QI_F    (QT * QSTR)
#define QTOT_F  (2 * QT * QSTR)                  // 17408 floats
#define KR_F    0
#define KI_F    (NT * QSTR)
#define VR_F    (2 * NT * QSTR)
#define VI_F    (2 * NT * QSTR + NT * VSTR)
#define STG_F   (2 * NT * QSTR + 2 * NT * VSTR)  // 17920 floats
#define SMEM_BYTES ((QTOT_F + 2 * STG_F) * 4)    // 212992

__device__ unsigned int g_ticket;
__global__ void reset_ticket_kernel() { g_ticket = 0u; }

__device__ __forceinline__ uint32_t cvta_s(const void* p) {
    uint32_t a;
    asm("{ .reg .u64 t; cvta.to.shared.u64 t, %1; cvt.u32.u64 %0, t; }" : "=r"(a) : "l"(p));
    return a;
}
__device__ __forceinline__ void cpa16(uint32_t dst, const void* src) {
    asm volatile("cp.async.ca.shared.global [%0], [%1], 16;" :: "r"(dst), "l"(src));
}
#define CP_COMMIT() asm volatile("cp.async.commit_group;" ::: "memory")
#define CP_WAIT0()  asm volatile("cp.async.wait_group 0;" ::: "memory")

__device__ __forceinline__ uint32_t f2tf(float x) {
    uint32_t r; asm("cvt.rna.tf32.f32 %0, %1;" : "=r"(r) : "f"(x)); return r;
}
__device__ __forceinline__ void mma8(float* d, const uint32_t* a, uint32_t b0, uint32_t b1) {
    asm volatile(
        "mma.sync.aligned.m16n8k8.row.col.f32.tf32.tf32.f32 "
        "{%0,%1,%2,%3}, {%4,%5,%6,%7}, {%8,%9}, {%0,%1,%2,%3};"
        : "+f"(d[0]), "+f"(d[1]), "+f"(d[2]), "+f"(d[3])
        : "r"(a[0]), "r"(a[1]), "r"(a[2]), "r"(a[3]), "r"(b0), "r"(b1));
}

// C-fragment (cols {2j,2j+1}) -> A-fragment (cols {j,j+4}) lane permutation.
__device__ __forceinline__ void xform(const float* c, uint32_t* a, int lane) {
    int j  = lane & 3;
    int s0 = (lane & ~3) | (j >> 1);
    int s1 = s0 + 2;
    float y00 = __shfl_sync(~0u, c[0], s0), y01 = __shfl_sync(~0u, c[1], s0);
    float y10 = __shfl_sync(~0u, c[0], s1), y11 = __shfl_sync(~0u, c[1], s1);
    float y20 = __shfl_sync(~0u, c[2], s0), y21 = __shfl_sync(~0u, c[3], s0);
    float y30 = __shfl_sync(~0u, c[2], s1), y31 = __shfl_sync(~0u, c[3], s1);
    bool od = (j & 1);
    a[0] = f2tf(od ? y01 : y00);
    a[1] = f2tf(od ? y21 : y20);
    a[2] = f2tf(od ? y11 : y10);
    a[3] = f2tf(od ? y31 : y30);
}

__global__ __launch_bounds__(THREADS, 1)
void cv_attn_mma_kernel(
    const float* __restrict__ qr, const float* __restrict__ qi,
    const float* __restrict__ kr, const float* __restrict__ ki,
    const float* __restrict__ vr, const float* __restrict__ vi,
    float* __restrict__ out, long long plane)
{
    extern __shared__ float sm[];
    __shared__ int s_item;
    const uint32_t smb = cvta_s(sm);

    const int tid  = threadIdx.x;
    const int w    = tid >> 5;
    const int lane = tid & 31;
    const int g4   = lane >> 2;
    const int j4   = lane & 3;
    const int r0   = w * 16 + g4;

    for (;;) {
        if (tid == 0) s_item = (int)atomicAdd(&g_ticket, 1u);
        __syncthreads();
        const int item = s_item;
        if (item >= NITEMS) break;

        const int bh = item >> 4;            // consecutive items share head -> L2 reuse
        const int s0 = (item & 15) * QT;
        const long long bb = (long long)bh * S_LEN * DH;

        // ---- prologue: Q + stage 0 via cp.async ----
        #pragma unroll
        for (int it = 0; it < 16; ++it) {
            int i = tid + it * THREADS;
            int pl = i >> 11, jj = i & 2047;
            int r = jj >> 4, c = jj & 15;
            const float* g = (pl ? qi : qr) + bb + (long long)(s0 + r) * DH + c * 4;
            cpa16(smb + ((pl ? QI_F : QR_F) + r * QSTR + c * 4) * 4, g);
        }
        {
            const uint32_t sbase = smb + QTOT_F * 4;
            #pragma unroll
            for (int it = 0; it < 16; ++it) {
                int i = tid + it * THREADS;
                int half = i >> 11, pl = (i >> 10) & 1, jj = i & 1023;
                int r = jj >> 4, c = jj & 15;
                const float* g; uint32_t foff;
                if (half == 0) {
                    g = (pl ? ki : kr) + bb + (long long)r * DH + c * 4;
                    foff = (pl ? KI_F : KR_F) + r * QSTR + c * 4;
                } else {
                    g = (pl ? vi : vr) + bb + (long long)r * DH + c * 4;
                    foff = (pl ? VI_F : VR_F) + r * VSTR + c * 4;
                }
                cpa16(sbase + foff * 4, g);
            }
        }
        CP_COMMIT();

        float o1[8][4], o2[8][4], o3[8][4];
        #pragma unroll
        for (int nb = 0; nb < 8; ++nb)
            #pragma unroll
            for (int c = 0; c < 4; ++c) { o1[nb][c] = 0.f; o2[nb][c] = 0.f; o3[nb][c] = 0.f; }
        float l0 = 0.f, l1 = 0.f;

        for (int t = 0; t < NTILES; ++t) {
            CP_WAIT0();
            __syncthreads();

            float* st = sm + QTOT_F + (t & 1) * STG_F;
            // ---- in-place fp32 -> tf32 conversion (once per tile; Q once per item) ----
            if (t == 0) {
                for (int i = tid; i < QTOT_F / 4; i += THREADS) {
                    float4 v = ((float4*)sm)[i];
                    ((float4*)sm)[i] = make_float4(
                        __uint_as_float(f2tf(v.x)), __uint_as_float(f2tf(v.y)),
                        __uint_as_float(f2tf(v.z)), __uint_as_float(f2tf(v.w)));
                }
            }
            for (int i = tid; i < STG_F / 4; i += THREADS) {
                float4 v = ((float4*)st)[i];
                ((float4*)st)[i] = make_float4(
                    __uint_as_float(f2tf(v.x)), __uint_as_float(f2tf(v.y)),
                    __uint_as_float(f2tf(v.z)), __uint_as_float(f2tf(v.w)));
            }
            __syncthreads();

            if (t + 1 < NTILES) {   // prefetch next stage into other buffer
                const uint32_t sbase = smb + (QTOT_F + ((t + 1) & 1) * STG_F) * 4;
                #pragma unroll
                for (int it = 0; it < 16; ++it) {
                    int i = tid + it * THREADS;
                    int half = i >> 11, pl = (i >> 10) & 1, jj = i & 1023;
                    int r = jj >> 4, c = jj & 15;
                    const float* g; uint32_t foff;
                    if (half == 0) {
                        g = (pl ? ki : kr) + bb + (long long)((t + 1) * NT + r) * DH + c * 4;
                        foff = (pl ? KI_F : KR_F) + r * QSTR + c * 4;
                    } else {
                        g = (pl ? vi : vr) + bb + (long long)((t + 1) * NT + r) * DH + c * 4;
                        foff = (pl ? VI_F : VR_F) + r * VSTR + c * 4;
                    }
                    cpa16(sbase + foff * 4, g);
                }
                CP_COMMIT();
            }

            const uint32_t* Kr = (const uint32_t*)(st + KR_F);
            const uint32_t* Ki = (const uint32_t*)(st + KI_F);
            const uint32_t* Vr = (const uint32_t*)(st + VR_F);
            const uint32_t* Vi = (const uint32_t*)(st + VI_F);
            const uint32_t* Qr = (const uint32_t*)(sm + QR_F);
            const uint32_t* Qi = (const uint32_t*)(sm + QI_F);

            // ---- GEMM1 (Karatsuba): m1=QrKr, m2=QiKi, m3=(Qr+Qi)(Kr+Ki) ----
            float s1[8][4], s2[8][4], s3[8][4];
            #pragma unroll
            for (int nb = 0; nb < 8; ++nb)
                #pragma unroll
                for (int c = 0; c < 4; ++c) { s1[nb][c] = 0.f; s2[nb][c] = 0.f; s3[nb][c] = 0.f; }

            #pragma unroll
            for (int ks = 0; ks < 8; ++ks) {
                const int d0 = ks * 8 + j4;
                uint32_t aqr[4], aqi[4], aqs[4];
                aqr[0] = Qr[ r0      * QSTR + d0    ];
                aqr[1] = Qr[(r0 + 8) * QSTR + d0    ];
                aqr[2] = Qr[ r0      * QSTR + d0 + 4];
                aqr[3] = Qr[(r0 + 8) * QSTR + d0 + 4];
                aqi[0] = Qi[ r0      * QSTR + d0    ];
                aqi[1] = Qi[(r0 + 8) * QSTR + d0    ];
                aqi[2] = Qi[ r0      * QSTR + d0 + 4];
                aqi[3] = Qi[(r0 + 8) * QSTR + d0 + 4];
                #pragma unroll
                for (int k = 0; k < 4; ++k)
                    aqs[k] = f2tf(__uint_as_float(aqr[k]) + __uint_as_float(aqi[k]));

                #pragma unroll
                for (int nb = 0; nb < 8; ++nb) {
                    const int ka = (nb * 8 + g4) * QSTR + ks * 8 + j4;
                    uint32_t br0 = Kr[ka], br1 = Kr[ka + 4];
                    uint32_t bi0 = Ki[ka], bi1 = Ki[ka + 4];
                    uint32_t bs0 = f2tf(__uint_as_float(br0) + __uint_as_float(bi0));
                    uint32_t bs1 = f2tf(__uint_as_float(br1) + __uint_as_float(bi1));
                    mma8(s1[nb], aqr, br0, br1);
                    mma8(s2[nb], aqi, bi0, bi1);
                    mma8(s3[nb], aqs, bs0, bs1);
                }
            }

            // ---- epilogue: combine + cv-softmax; P back into s1(re)/s2(im) ----
            #pragma unroll
            for (int nb = 0; nb < 8; ++nb) {
                #pragma unroll
                for (int c = 0; c < 4; ++c) {
                    float m1 = s1[nb][c], m2 = s2[nb][c], m3 = s3[nb][c];
                    float re = m1 - m2;
                    float im = m3 - m1 - m2;
                    float mm2 = fmaxf(fmaf(re, re, im * im), 1e-24f);
                    float inv = rsqrtf(mm2);
                    float mag = mm2 * inv;
                    float e   = __expf(0.125f * mag);
                    if (c < 2) l0 += e; else l1 += e;
                    float p = e * inv;
                    s1[nb][c] = re * p;
                    s2[nb][c] = im * p;
                }
            }

            // ---- GEMM2 (Karatsuba): o1+=PrVr, o2+=PiVi, o3+=(Pr+Pi)(Vr+Vi) ----
            #pragma unroll
            for (int ks = 0; ks < 8; ++ks) {
                uint32_t apr[4], api[4], aps[4];
                xform(s1[ks], apr, lane);
                xform(s2[ks], api, lane);
                #pragma unroll
                for (int k = 0; k < 4; ++k)
                    aps[k] = f2tf(__uint_as_float(apr[k]) + __uint_as_float(api[k]));

                #pragma unroll
                for (int nb = 0; nb < 8; ++nb) {
                    const int va = (ks * 8 + j4) * VSTR + nb * 8 + g4;
                    uint32_t vr0 = Vr[va], vr1 = Vr[va + 4 * VSTR];
                    uint32_t vi0 = Vi[va], vi1 = Vi[va + 4 * VSTR];
                    uint32_t vs0 = f2tf(__uint_as_float(vr0) + __uint_as_float(vi0));
                    uint32_t vs1 = f2tf(__uint_as_float(vr1) + __uint_as_float(vi1));
                    mma8(o1[nb], apr, vr0, vr1);
                    mma8(o2[nb], api, vi0, vi1);
                    mma8(o3[nb], aps, vs0, vs1);
                }
            }
        }

        __syncthreads();   // stage/Q region free; reuse Q region as output stage

        l0 += __shfl_xor_sync(~0u, l0, 1); l0 += __shfl_xor_sync(~0u, l0, 2);
        l1 += __shfl_xor_sync(~0u, l1, 1); l1 += __shfl_xor_sync(~0u, l1, 2);
        float il0 = 1.0f / l0, il1 = 1.0f / l1;

        float* stR = sm + QR_F;
        float* stI = sm + QI_F;
        #pragma unroll
        for (int nb = 0; nb < 8; ++nb) {
            int d0 = nb * 8 + 2 * j4;
            #pragma unroll
            for (int c = 0; c < 4; ++c) {
                float ore = o1[nb][c] - o2[nb][c];
                float oim = o3[nb][c] - o1[nb][c] - o2[nb][c];
                int rr = (c < 2) ? r0 : r0 + 8;
                float il = (c < 2) ? il0 : il1;
                stR[rr * QSTR + d0 + (c & 1)] = ore * il;
                stI[rr * QSTR + d0 + (c & 1)] = oim * il;
            }
        }
        __syncthreads();

        for (int i = tid; i < QT * 16; i += THREADS) {
            int r = i >> 4, c = i & 15;
            long long ob = bb + (long long)(s0 + r) * DH + c * 4;
            *(float4*)(out + ob)         = *(float4*)(stR + r * QSTR + c * 4);
            *(float4*)(out + plane + ob) = *(float4*)(stI + r * QSTR + c * 4);
        }
        __syncthreads();   // output read before next item's Q overwrites stage
    }
}

extern "C" void kernel_launch(void* const* d_in, const int* in_sizes, int n_in,
                              void* d_out, int out_size) {
    const float* qr = (const float*)d_in[0];
    const float* qi = (const float*)d_in[1];
    const float* kr = (const float*)d_in[2];
    const float* ki = (const float*)d_in[3];
    const float* vr = (const float*)d_in[4];
    const float* vi = (const float*)d_in[5];

    const long long plane = (long long)in_sizes[0];   // B*H*S*D

    static int configured = 0;
    if (!configured) {
        cudaFuncSetAttribute(cv_attn_mma_kernel,
                             cudaFuncAttributeMaxDynamicSharedMemorySize, SMEM_BYTES);
        configured = 1;
    }

    reset_ticket_kernel<<<1, 1>>>();
    cv_attn_mma_kernel<<<GRID, THREADS, SMEM_BYTES>>>(qr, qi, kr, ki, vr, vi,
                                                      (float*)d_out, plane);
}

// round 7
// speedup vs baseline: 1.8981x; 1.8981x over previous
#include <cuda_runtime.h>
#include <cstdint>

// Complex attention via mma.sync fp16 m16n8k16 (same mantissa as tf32, 2x rate).
// S = complex (Q/t)K^T ; P = exp(|S|)*S/|S| ; O = P@V ; out = O / sum(exp|S|).

#define S_LEN   2048
#define DH      64
#define QT      128
#define NT      64
#define NTILES  (S_LEN / NT)
#define THREADS 256
#define NITEMS  512
#define GRID    152
#define STRH    88              // halves per smem row
#define ROWB    (STRH * 2)      // 176 bytes

#define QR_B    0
#define QI_B    (QT * ROWB)             // 22528
#define KR_B    (2 * QT * ROWB)         // 45056
#define KI_B    (KR_B + NT * ROWB)      // 56320
#define VTR_B   (KI_B + NT * ROWB)      // 67584
#define VTI_B   (VTR_B + DH * ROWB)     // 78848
#define SMEM_BYTES (VTI_B + DH * ROWB)  // 90112

__device__ unsigned int g_ticket;
__global__ void reset_ticket_kernel() { g_ticket = 0u; }

__device__ __forceinline__ uint32_t pkh(float lo, float hi) {
    uint32_t d; asm("cvt.rn.f16x2.f32 %0, %1, %2;" : "=r"(d) : "f"(hi), "f"(lo)); return d;
}
__device__ __forceinline__ void mma16(float* d, const uint32_t* a, uint32_t b0, uint32_t b1) {
    asm volatile(
        "mma.sync.aligned.m16n8k16.row.col.f32.f16.f16.f32 "
        "{%0,%1,%2,%3}, {%4,%5,%6,%7}, {%8,%9}, {%0,%1,%2,%3};"
        : "+f"(d[0]), "+f"(d[1]), "+f"(d[2]), "+f"(d[3])
        : "r"(a[0]), "r"(a[1]), "r"(a[2]), "r"(a[3]), "r"(b0), "r"(b1));
}

__global__ __launch_bounds__(THREADS, 1)
void cv_attn_h_kernel(
    const float* __restrict__ qr, const float* __restrict__ qi,
    const float* __restrict__ kr, const float* __restrict__ ki,
    const float* __restrict__ vr, const float* __restrict__ vi,
    float* __restrict__ out, long long plane)
{
    extern __shared__ char sm[];
    __shared__ int s_item;

    const int tid  = threadIdx.x;
    const int w    = tid >> 5;
    const int lane = tid & 31;
    const int g4   = lane >> 2;
    const int j4   = lane & 3;
    const int r0   = w * 16 + g4;

    const int kkey = tid >> 2, kdb = (tid & 3) * 16;    // K: 16 d of one key
    const int vpl  = w & 1,    vkq = w >> 1;            // V: warp = plane x key-quarter
    const uint32_t qfo = (uint32_t)(r0 * ROWB + 4 * j4);
    const uint32_t kfo = (uint32_t)(g4 * ROWB + 4 * j4);

    for (;;) {
        if (tid == 0) s_item = (int)atomicAdd(&g_ticket, 1u);
        __syncthreads();
        const int item = s_item;
        if (item >= NITEMS) break;

        const int bh = item >> 4;
        const int s0 = (item & 15) * QT;
        const long long bb = (long long)bh * S_LEN * DH;

        // ---- prefetch K(0) into registers ----
        float4 k0[4], k1[4];
        {
            const float* g0 = kr + bb + (long long)kkey * DH + kdb;
            const float* g1 = ki + bb + (long long)kkey * DH + kdb;
            #pragma unroll
            for (int j = 0; j < 4; ++j) k0[j] = *(const float4*)(g0 + j * 4);
            #pragma unroll
            for (int j = 0; j < 4; ++j) k1[j] = *(const float4*)(g1 + j * 4);
        }

        // ---- load Q (scaled by 1/8) -> half planes; 2 chunks of 16 d per thread ----
        {
            const int qrow = tid >> 1;
            const int qd0  = (tid & 1) * 32;
            #pragma unroll
            for (int hh = 0; hh < 2; ++hh) {
                const int qdb = qd0 + hh * 16;
                const float* g0 = qr + bb + (long long)(s0 + qrow) * DH + qdb;
                const float* g1 = qi + bb + (long long)(s0 + qrow) * DH + qdb;
                float4 a[4], b[4];
                #pragma unroll
                for (int j = 0; j < 4; ++j) a[j] = *(const float4*)(g0 + j * 4);
                #pragma unroll
                for (int j = 0; j < 4; ++j) b[j] = *(const float4*)(g1 + j * 4);
                #pragma unroll
                for (int j = 0; j < 4; ++j) {
                    a[j].x *= 0.125f; a[j].y *= 0.125f; a[j].z *= 0.125f; a[j].w *= 0.125f;
                    b[j].x *= 0.125f; b[j].y *= 0.125f; b[j].z *= 0.125f; b[j].w *= 0.125f;
                }
                char* d0 = sm + QR_B + qrow * ROWB + qdb * 2;
                char* d1 = sm + QI_B + qrow * ROWB + qdb * 2;
                #pragma unroll
                for (int h = 0; h < 2; ++h) {
                    uint4 u;
                    u.x = pkh(a[h*2].x, a[h*2].y);     u.y = pkh(a[h*2].z, a[h*2].w);
                    u.z = pkh(a[h*2+1].x, a[h*2+1].y); u.w = pkh(a[h*2+1].z, a[h*2+1].w);
                    *(uint4*)(d0 + h * 16) = u;
                    uint4 v;
                    v.x = pkh(b[h*2].x, b[h*2].y);     v.y = pkh(b[h*2].z, b[h*2].w);
                    v.z = pkh(b[h*2+1].x, b[h*2+1].y); v.w = pkh(b[h*2+1].z, b[h*2+1].w);
                    *(uint4*)(d1 + h * 16) = v;
                }
            }
        }

        float ore[8][4], oim[8][4];
        #pragma unroll
        for (int nb = 0; nb < 8; ++nb)
            #pragma unroll
            for (int c = 0; c < 4; ++c) { ore[nb][c] = 0.f; oim[nb][c] = 0.f; }
        float l0 = 0.f, l1 = 0.f;

        for (int t = 0; t < NTILES; ++t) {
            // ---- STS K(t) from registers ----
            {
                char* d0 = sm + KR_B + kkey * ROWB + kdb * 2;
                char* d1 = sm + KI_B + kkey * ROWB + kdb * 2;
                #pragma unroll
                for (int h = 0; h < 2; ++h) {
                    uint4 u;
                    u.x = pkh(k0[h*2].x, k0[h*2].y);     u.y = pkh(k0[h*2].z, k0[h*2].w);
                    u.z = pkh(k0[h*2+1].x, k0[h*2+1].y); u.w = pkh(k0[h*2+1].z, k0[h*2+1].w);
                    *(uint4*)(d0 + h * 16) = u;
                    uint4 v;
                    v.x = pkh(k1[h*2].x, k1[h*2].y);     v.y = pkh(k1[h*2].z, k1[h*2].w);
                    v.z = pkh(k1[h*2+1].x, k1[h*2+1].y); v.w = pkh(k1[h*2+1].z, k1[h*2+1].w);
                    *(uint4*)(d1 + h * 16) = v;
                }
            }
            __syncthreads();

            // ---- issue V(t) LDG (consumed after GEMM1) ----
            float2 vv[16];
            {
                const float* g = (vpl ? vi : vr) + bb
                               + (long long)(t * NT + vkq * 16) * DH + 2 * lane;
                #pragma unroll
                for (int j = 0; j < 16; ++j) vv[j] = *(const float2*)(g + j * DH);
            }

            // ---- GEMM1: S[16 x 64] complex ----
            float sre[8][4], sim[8][4];
            #pragma unroll
            for (int nb = 0; nb < 8; ++nb)
                #pragma unroll
                for (int c = 0; c < 4; ++c) { sre[nb][c] = 0.f; sim[nb][c] = 0.f; }

            #pragma unroll
            for (int ks = 0; ks < 4; ++ks) {
                uint32_t qa[4], qb[4], nqb[4];
                const char* qp = sm + QR_B + qfo + ks * 32;
                qa[0] = *(const uint32_t*)(qp);
                qa[1] = *(const uint32_t*)(qp + 8 * ROWB);
                qa[2] = *(const uint32_t*)(qp + 16);
                qa[3] = *(const uint32_t*)(qp + 8 * ROWB + 16);
                const char* qip = sm + QI_B + qfo + ks * 32;
                qb[0] = *(const uint32_t*)(qip);
                qb[1] = *(const uint32_t*)(qip + 8 * ROWB);
                qb[2] = *(const uint32_t*)(qip + 16);
                qb[3] = *(const uint32_t*)(qip + 8 * ROWB + 16);
                #pragma unroll
                for (int k = 0; k < 4; ++k) nqb[k] = qb[k] ^ 0x80008000u;

                #pragma unroll
                for (int nb = 0; nb < 8; ++nb) {
                    const char* kp  = sm + KR_B + kfo + nb * (8 * ROWB) + ks * 32;
                    const char* kip = sm + KI_B + kfo + nb * (8 * ROWB) + ks * 32;
                    uint32_t br0 = *(const uint32_t*)(kp);
                    uint32_t br1 = *(const uint32_t*)(kp + 16);
                    uint32_t bi0 = *(const uint32_t*)(kip);
                    uint32_t bi1 = *(const uint32_t*)(kip + 16);
                    mma16(sre[nb], qa,  br0, br1);
                    mma16(sre[nb], nqb, bi0, bi1);
                    mma16(sim[nb], qa,  bi0, bi1);
                    mma16(sim[nb], qb,  br0, br1);
                }
            }

            // ---- cv-softmax epilogue ----
            #pragma unroll
            for (int nb = 0; nb < 8; ++nb) {
                #pragma unroll
                for (int c = 0; c < 4; ++c) {
                    float re = sre[nb][c], im = sim[nb][c];
                    float m2  = fmaxf(fmaf(re, re, im * im), 1e-24f);
                    float inv = rsqrtf(m2);
                    float mag = m2 * inv;
                    float e   = __expf(mag);          // Q pre-scaled by 1/t
                    if (c < 2) l0 += e; else l1 += e;
                    float p = e * inv;
                    sre[nb][c] = re * p;
                    sim[nb][c] = im * p;
                }
            }

            // ---- STS V(t) transposed to Vt[d][key] half ----
            {
                char* d0 = sm + (vpl ? VTI_B : VTR_B) + (2 * lane) * ROWB + vkq * 32;
                uint4 a;
                a.x = pkh(vv[0].x, vv[1].x);  a.y = pkh(vv[2].x, vv[3].x);
                a.z = pkh(vv[4].x, vv[5].x);  a.w = pkh(vv[6].x, vv[7].x);
                *(uint4*)(d0) = a;
                uint4 b;
                b.x = pkh(vv[8].x, vv[9].x);   b.y = pkh(vv[10].x, vv[11].x);
                b.z = pkh(vv[12].x, vv[13].x); b.w = pkh(vv[14].x, vv[15].x);
                *(uint4*)(d0 + 16) = b;
                char* d1 = d0 + ROWB;
                uint4 c;
                c.x = pkh(vv[0].y, vv[1].y);  c.y = pkh(vv[2].y, vv[3].y);
                c.z = pkh(vv[4].y, vv[5].y);  c.w = pkh(vv[6].y, vv[7].y);
                *(uint4*)(d1) = c;
                uint4 e;
                e.x = pkh(vv[8].y, vv[9].y);   e.y = pkh(vv[10].y, vv[11].y);
                e.z = pkh(vv[12].y, vv[13].y); e.w = pkh(vv[14].y, vv[15].y);
                *(uint4*)(d1 + 16) = e;
            }
            __syncthreads();

            // ---- prefetch K(t+1) ----
            if (t + 1 < NTILES) {
                const float* g0 = kr + bb + (long long)((t + 1) * NT + kkey) * DH + kdb;
                const float* g1 = ki + bb + (long long)((t + 1) * NT + kkey) * DH + kdb;
                #pragma unroll
                for (int j = 0; j < 4; ++j) k0[j] = *(const float4*)(g0 + j * 4);
                #pragma unroll
                for (int j = 0; j < 4; ++j) k1[j] = *(const float4*)(g1 + j * 4);
            }

            // ---- GEMM2: O += P @ V (A-frag = packed C-frag pairs) ----
            #pragma unroll
            for (int ks = 0; ks < 4; ++ks) {
                uint32_t pa[4], pb[4], npb[4];
                pa[0] = pkh(sre[2*ks][0],   sre[2*ks][1]);
                pa[1] = pkh(sre[2*ks][2],   sre[2*ks][3]);
                pa[2] = pkh(sre[2*ks+1][0], sre[2*ks+1][1]);
                pa[3] = pkh(sre[2*ks+1][2], sre[2*ks+1][3]);
                pb[0] = pkh(sim[2*ks][0],   sim[2*ks][1]);
                pb[1] = pkh(sim[2*ks][2],   sim[2*ks][3]);
                pb[2] = pkh(sim[2*ks+1][0], sim[2*ks+1][1]);
                pb[3] = pkh(sim[2*ks+1][2], sim[2*ks+1][3]);
                #pragma unroll
                for (int k = 0; k < 4; ++k) npb[k] = pb[k] ^ 0x80008000u;

                #pragma unroll
                for (int nb = 0; nb < 8; ++nb) {
                    const char* vp  = sm + VTR_B + kfo + nb * (8 * ROWB) + ks * 32;
                    const char* vip = sm + VTI_B + kfo + nb * (8 * ROWB) + ks * 32;
                    uint32_t vr0 = *(const uint32_t*)(vp);
                    uint32_t vr1 = *(const uint32_t*)(vp + 16);
                    uint32_t vi0 = *(const uint32_t*)(vip);
                    uint32_t vi1 = *(const uint32_t*)(vip + 16);
                    mma16(ore[nb], pa,  vr0, vr1);
                    mma16(ore[nb], npb, vi0, vi1);
                    mma16(oim[nb], pa,  vi0, vi1);
                    mma16(oim[nb], pb,  vr0, vr1);
                }
            }
        }

        __syncthreads();   // all tiles done; smem reusable as output stage

        l0 += __shfl_xor_sync(~0u, l0, 1); l0 += __shfl_xor_sync(~0u, l0, 2);
        l1 += __shfl_xor_sync(~0u, l1, 1); l1 += __shfl_xor_sync(~0u, l1, 2);
        const float il0 = 1.0f / l0, il1 = 1.0f / l1;

        float* stg = (float*)sm;            // [128][132]: cols 0..63 re, 64..127 im
        #pragma unroll
        for (int nb = 0; nb < 8; ++nb) {
            const int d0 = nb * 8 + 2 * j4;
            stg[ r0      * 132 + d0    ]    = ore[nb][0] * il0;
            stg[ r0      * 132 + d0 + 1]    = ore[nb][1] * il0;
            stg[(r0 + 8) * 132 + d0    ]    = ore[nb][2] * il1;
            stg[(r0 + 8) * 132 + d0 + 1]    = ore[nb][3] * il1;
            stg[ r0      * 132 + 64 + d0]   = oim[nb][0] * il0;
            stg[ r0      * 132 + 64 + d0+1] = oim[nb][1] * il0;
            stg[(r0 + 8) * 132 + 64 + d0]   = oim[nb][2] * il1;
            stg[(r0 + 8) * 132 + 64 + d0+1] = oim[nb][3] * il1;
        }
        __syncthreads();

        for (int i = tid; i < QT * 32; i += THREADS) {
            const int row = i >> 5, c = i & 31;
            float4 v = *(const float4*)(stg + row * 132 + c * 4);
            if (c < 16)
                *(float4*)(out + bb + (long long)(s0 + row) * DH + c * 4) = v;
            else
                *(float4*)(out + plane + bb + (long long)(s0 + row) * DH + (c - 16) * 4) = v;
        }
        __syncthreads();   // stage consumed before next item's Q store
    }
}

extern "C" void kernel_launch(void* const* d_in, const int* in_sizes, int n_in,
                              void* d_out, int out_size) {
    const float* qr = (const float*)d_in[0];
    const float* qi = (const float*)d_in[1];
    const float* kr = (const float*)d_in[2];
    const float* ki = (const float*)d_in[3];
    const float* vr = (const float*)d_in[4];
    const float* vi = (const float*)d_in[5];

    const long long plane = (long long)in_sizes[0];   // B*H*S*D

    static int configured = 0;
    if (!configured) {
        cudaFuncSetAttribute(cv_attn_h_kernel,
                             cudaFuncAttributeMaxDynamicSharedMemorySize, SMEM_BYTES);
        configured = 1;
    }

    reset_ticket_kernel<<<1, 1>>>();
    cv_attn_h_kernel<<<GRID, THREADS, SMEM_BYTES>>>(qr, qi, kr, ki, vr, vi,
                                                    (float*)d_out, plane);
}